// round 1
// baseline (speedup 1.0000x reference)
#include <cuda_runtime.h>
#include <math.h>

// Problem constants
#define Bn 8
#define Nn 2048
#define Cn 1024
#define Mrows (Bn*Nn)   // 16384
#define JT1 16          // number of 64-wide j tiles in GEMM1 (1024/64)

// ---------------- scratch (device globals; no cudaMalloc allowed) ----------------
__device__ float g_v[(size_t)Mrows * Cn];           // 64 MB: v = x @ Wv
__device__ float g_stats[(size_t)JT1 * Mrows * 5];  // per-jtile partial row stats
__device__ float g_mpart[16 * Bn * Cn];             // partial column sums of x over n
__device__ float g_A[Mrows];                        // attn_base / A
__device__ float g_w[Mrows];                        // softmax weights
__device__ float g_chw[Bn * Cn];                    // channel gate

// =====================================================================
// GEMM1: qkv = x @ qkv_w, fused epilogue:
//   - writes v (cols 2048:3072 of qkv) to g_v
//   - reduces per-row stats of q (cols 0:1024) and k (cols 1024:2048):
//     Sq, Sk, Sqq, Skk, Sqk  -> deterministic per-jtile partials
// Block tile: 128 rows x 64 cols (x3 matrices), BK=16, 256 threads,
// per-thread micro tile 8x4 per matrix (96 fp32 accumulators).
// =====================================================================
__global__ __launch_bounds__(256, 1)
void k_gemm1(const float* __restrict__ x, const float* __restrict__ w)
{
    const int tid = threadIdx.x;
    const int bx = blockIdx.x;          // j tile 0..15
    const int by = blockIdx.y;          // row tile 0..127
    const int row0 = by * 128;
    const int j0   = bx * 64;

    __shared__ float As[16][128];       // [k][m] transposed
    __shared__ float Bs[3][16][64];     // q,k,v weight tiles

    const int tx = tid & 15;            // 0..15 -> col group
    const int ty = tid >> 4;            // 0..15 -> row group

    float accq[8][4]; float acck[8][4]; float accv[8][4];
    #pragma unroll
    for (int i = 0; i < 8; i++)
        #pragma unroll
        for (int j = 0; j < 4; j++) { accq[i][j] = 0.f; acck[i][j] = 0.f; accv[i][j] = 0.f; }

    for (int k0 = 0; k0 < 1024; k0 += 16) {
        // ---- load A tile (128 x 16), transpose into As[k][m] ----
        #pragma unroll
        for (int l = 0; l < 2; l++) {
            int f = tid + l * 256;              // 0..511
            int r = f >> 2;                     // row 0..127
            int kk = (f & 3) * 4;               // k offset {0,4,8,12}
            float4 a = *(const float4*)(x + (size_t)(row0 + r) * 1024 + k0 + kk);
            As[kk + 0][r] = a.x; As[kk + 1][r] = a.y;
            As[kk + 2][r] = a.z; As[kk + 3][r] = a.w;
        }
        // ---- load B tiles (3 x 16 x 64) ----
        {
            int kk = tid >> 4;                  // 0..15
            int j4 = (tid & 15) * 4;            // 0..60
            const float* wp = w + (size_t)(k0 + kk) * 3072 + j0 + j4;
            #pragma unroll
            for (int m = 0; m < 3; m++) {
                float4 bvv = *(const float4*)(wp + m * 1024);
                *(float4*)&Bs[m][kk][j4] = bvv;
            }
        }
        __syncthreads();

        #pragma unroll
        for (int kk = 0; kk < 16; kk++) {
            float4 a0 = *(float4*)&As[kk][ty * 8];
            float4 a1 = *(float4*)&As[kk][ty * 8 + 4];
            float aa[8] = {a0.x, a0.y, a0.z, a0.w, a1.x, a1.y, a1.z, a1.w};
            float4 q4 = *(float4*)&Bs[0][kk][tx * 4];
            float4 k4 = *(float4*)&Bs[1][kk][tx * 4];
            float4 v4 = *(float4*)&Bs[2][kk][tx * 4];
            float bq[4] = {q4.x, q4.y, q4.z, q4.w};
            float bk[4] = {k4.x, k4.y, k4.z, k4.w};
            float bv[4] = {v4.x, v4.y, v4.z, v4.w};
            #pragma unroll
            for (int i = 0; i < 8; i++) {
                #pragma unroll
                for (int j = 0; j < 4; j++) {
                    accq[i][j] = fmaf(aa[i], bq[j], accq[i][j]);
                    acck[i][j] = fmaf(aa[i], bk[j], acck[i][j]);
                    accv[i][j] = fmaf(aa[i], bv[j], accv[i][j]);
                }
            }
        }
        __syncthreads();
    }

    // ---- write v ----
    #pragma unroll
    for (int i = 0; i < 8; i++) {
        float4 vv = {accv[i][0], accv[i][1], accv[i][2], accv[i][3]};
        *(float4*)(g_v + (size_t)(row0 + ty * 8 + i) * 1024 + j0 + tx * 4) = vv;
    }

    // ---- per-row stats, reduce across the 16 tx lanes (half-warp shuffle) ----
    #pragma unroll
    for (int i = 0; i < 8; i++) {
        float sq = 0.f, sk = 0.f, sqq = 0.f, skk = 0.f, sqk = 0.f;
        #pragma unroll
        for (int j = 0; j < 4; j++) {
            float q = accq[i][j], k = acck[i][j];
            sq += q; sk += k; sqq += q * q; skk += k * k; sqk += q * k;
        }
        #pragma unroll
        for (int off = 8; off > 0; off >>= 1) {
            sq  += __shfl_xor_sync(0xffffffffu, sq,  off);
            sk  += __shfl_xor_sync(0xffffffffu, sk,  off);
            sqq += __shfl_xor_sync(0xffffffffu, sqq, off);
            skk += __shfl_xor_sync(0xffffffffu, skk, off);
            sqk += __shfl_xor_sync(0xffffffffu, sqk, off);
        }
        if (tx == 0) {
            float* d = g_stats + ((size_t)bx * Mrows + row0 + ty * 8 + i) * 5;
            d[0] = sq; d[1] = sk; d[2] = sqq; d[3] = skk; d[4] = sqk;
        }
    }
}

// =====================================================================
// attn_base from stats (SSIM-like formula), per row.
// =====================================================================
__global__ void k_attn(const float* __restrict__ c1p, const float* __restrict__ c2p)
{
    int row = blockIdx.x * 256 + threadIdx.x;
    float S0 = 0.f, S1 = 0.f, S2 = 0.f, S3 = 0.f, S4 = 0.f;
    #pragma unroll
    for (int p = 0; p < JT1; p++) {
        const float* d = g_stats + ((size_t)p * Mrows + row) * 5;
        S0 += d[0]; S1 += d[1]; S2 += d[2]; S3 += d[3]; S4 += d[4];
    }
    const float c1 = *c1p, c2 = *c2p;
    const float invC = 1.0f / (float)Cn;
    const float invcm1 = 1.0f / (float)(Cn - 1);
    float muq = S0 * invC, muk = S1 * invC;
    float sqk = (S4 - (float)Cn * muq * muk) * invcm1;
    float sq2 = (S2 - (float)Cn * muq * muq) * invcm1;
    float sk2 = (S3 - (float)Cn * muk * muk) * invcm1;
    float num = (2.f * muq * muk + c1) * (2.f * sqk + c2);
    float den = (muq * muq + muk * muk + c1) * (sq2 + sk2 + c2);
    float r = num / (den + 1e-7f);
    g_A[row] = r * r;
}

// =====================================================================
// column-mean of x over n (partials over 16 n-chunks for determinism)
// =====================================================================
__global__ void k_mean(const float* __restrict__ x)
{
    int p = blockIdx.x;     // n chunk 0..15
    int b = blockIdx.y;     // batch
    int c = threadIdx.x;    // 0..1023
    const float* xp = x + ((size_t)b * Nn + p * 128) * Cn + c;
    float s = 0.f;
    #pragma unroll 4
    for (int n = 0; n < 128; n++) s += xp[(size_t)n * Cn];
    g_mpart[(p * Bn + b) * Cn + c] = s;
}

// =====================================================================
// channel gate: ch_w = sigmoid(relu(m @ W1 + b1) @ W2 + b2), one block/batch
// =====================================================================
__global__ __launch_bounds__(256)
void k_ch(const float* __restrict__ w1, const float* __restrict__ b1,
          const float* __restrict__ w2, const float* __restrict__ b2)
{
    const int b = blockIdx.x, tid = threadIdx.x;
    __shared__ float m[1024];
    __shared__ float h[256];
    for (int c = tid; c < 1024; c += 256) {
        float s = 0.f;
        #pragma unroll
        for (int p = 0; p < 16; p++) s += g_mpart[(p * Bn + b) * Cn + c];
        m[c] = s * (1.0f / (float)Nn);
    }
    __syncthreads();
    {
        float acc = b1[tid];
        #pragma unroll 4
        for (int c = 0; c < 1024; c++) acc = fmaf(m[c], w1[c * 256 + tid], acc);
        h[tid] = fmaxf(acc, 0.f);
    }
    __syncthreads();
    for (int c = tid; c < 1024; c += 256) {
        float a = b2[c];
        #pragma unroll 4
        for (int j = 0; j < 256; j++) a = fmaf(h[j], w2[j * 1024 + c], a);
        g_chw[b * Cn + c] = 1.0f / (1.0f + expf(-a));
    }
}

// =====================================================================
// ODE step (conv1 -> GroupNorm(2 groups) -> relu -> conv2 -> +A),
// then sigmoid + softmax over N. One block per batch, 256 threads.
// =====================================================================
__device__ __forceinline__ float blk_sum(float v, float* red, int tid)
{
    red[tid] = v; __syncthreads();
    #pragma unroll
    for (int s = 128; s > 0; s >>= 1) {
        if (tid < s) red[tid] += red[tid + s];
        __syncthreads();
    }
    float r = red[0]; __syncthreads();
    return r;
}
__device__ __forceinline__ float blk_max(float v, float* red, int tid)
{
    red[tid] = v; __syncthreads();
    #pragma unroll
    for (int s = 128; s > 0; s >>= 1) {
        if (tid < s) red[tid] = fmaxf(red[tid], red[tid + s]);
        __syncthreads();
    }
    float r = red[0]; __syncthreads();
    return r;
}

__global__ __launch_bounds__(256)
void k_ode(const float* __restrict__ c1w, const float* __restrict__ gng,
           const float* __restrict__ gnb, const float* __restrict__ c2w,
           const float* __restrict__ c2b)
{
    const int b = blockIdx.x, tid = threadIdx.x;
    __shared__ float A[2048];
    __shared__ float h[4][2048];
    __shared__ float red[256];

    float w1[12], w2[12], gg[4], gb[4];
    #pragma unroll
    for (int t = 0; t < 12; t++) { w1[t] = c1w[t]; w2[t] = c2w[t]; }
    #pragma unroll
    for (int o = 0; o < 4; o++) { gg[o] = gng[o]; gb[o] = gnb[o]; }

    #pragma unroll
    for (int j = 0; j < 8; j++) { int n = tid + j * 256; A[n] = g_A[b * Nn + n]; }
    __syncthreads();

    // conv1 (zero pad) + group partial sums
    float s0 = 0.f, ss0 = 0.f, s1 = 0.f, ss1 = 0.f;
    #pragma unroll
    for (int j = 0; j < 8; j++) {
        int n = tid + j * 256;
        float am = (n > 0)    ? A[n - 1] : 0.f;
        float a0 = A[n];
        float ap = (n < 2047) ? A[n + 1] : 0.f;
        #pragma unroll
        for (int o = 0; o < 4; o++) {
            float v = am * w1[o * 3] + a0 * w1[o * 3 + 1] + ap * w1[o * 3 + 2];
            h[o][n] = v;
            if (o < 2) { s0 += v; ss0 += v * v; } else { s1 += v; ss1 += v * v; }
        }
    }
    float S0  = blk_sum(s0,  red, tid);
    float SS0 = blk_sum(ss0, red, tid);
    float S1  = blk_sum(s1,  red, tid);
    float SS1 = blk_sum(ss1, red, tid);
    const float inv = 1.0f / 4096.0f;
    float mu[2] = {S0 * inv, S1 * inv};
    float rs[2] = {rsqrtf(SS0 * inv - mu[0] * mu[0] + 1e-5f),
                   rsqrtf(SS1 * inv - mu[1] * mu[1] + 1e-5f)};

    // normalize + affine + relu (in place)
    #pragma unroll
    for (int j = 0; j < 8; j++) {
        int n = tid + j * 256;
        #pragma unroll
        for (int o = 0; o < 4; o++) {
            int g = o >> 1;
            float v = (h[o][n] - mu[g]) * rs[g] * gg[o] + gb[o];
            h[o][n] = v > 0.f ? v : 0.f;
        }
    }
    __syncthreads();

    // conv2 + residual (dt = 1) + sigmoid
    float fa[8];
    float c2bv = c2b[0];
    float mx = -1e30f;
    #pragma unroll
    for (int j = 0; j < 8; j++) {
        int n = tid + j * 256;
        float y = c2bv;
        #pragma unroll
        for (int o = 0; o < 4; o++) {
            float hm = (n > 0)    ? h[o][n - 1] : 0.f;
            float h0 = h[o][n];
            float hp = (n < 2047) ? h[o][n + 1] : 0.f;
            y += hm * w2[o * 3] + h0 * w2[o * 3 + 1] + hp * w2[o * 3 + 2];
        }
        float An = A[n] + y;
        float f = 1.0f / (1.0f + expf(-An));
        fa[j] = f;
        mx = fmaxf(mx, f);
    }

    // softmax over N
    float gmax = blk_max(mx, red, tid);
    float se = 0.f;
    #pragma unroll
    for (int j = 0; j < 8; j++) { fa[j] = expf(fa[j] - gmax); se += fa[j]; }
    float tot = blk_sum(se, red, tid);
    float invt = 1.0f / tot;
    #pragma unroll
    for (int j = 0; j < 8; j++) g_w[b * Nn + tid + j * 256] = fa[j] * invt;
}

// =====================================================================
// GEMM2: out = (w[row] * v[row,:] * ch_w[b,:]) @ proj_w + proj_b
// Block tile 128x128, BK=8, 256 threads, 8x8 micro tile.
// Scaling fused into A-tile load.
// =====================================================================
__global__ __launch_bounds__(256, 1)
void k_gemm2(const float* __restrict__ pw, const float* __restrict__ pb,
             float* __restrict__ out)
{
    const int tid = threadIdx.x;
    const int bx = blockIdx.x;          // j tile 0..7
    const int by = blockIdx.y;          // row tile 0..127
    const int row0 = by * 128;
    const int j0   = bx * 128;
    const int b    = row0 >> 11;        // row0 / 2048

    __shared__ float As[8][128];
    __shared__ float Bs[8][128];

    const int tx = tid & 15, ty = tid >> 4;
    const int ra = tid >> 1, ka = (tid & 1) * 4;
    const int kb = tid >> 5, jb = (tid & 31) * 4;
    const float wr = g_w[row0 + ra];

    float acc[8][8];
    #pragma unroll
    for (int i = 0; i < 8; i++)
        #pragma unroll
        for (int j = 0; j < 8; j++) acc[i][j] = 0.f;

    for (int k0 = 0; k0 < 1024; k0 += 8) {
        float4 v4 = *(const float4*)(g_v + (size_t)(row0 + ra) * 1024 + k0 + ka);
        float4 cw = *(const float4*)(g_chw + b * Cn + k0 + ka);
        As[ka + 0][ra] = v4.x * wr * cw.x;
        As[ka + 1][ra] = v4.y * wr * cw.y;
        As[ka + 2][ra] = v4.z * wr * cw.z;
        As[ka + 3][ra] = v4.w * wr * cw.w;
        float4 b4 = *(const float4*)(pw + (size_t)(k0 + kb) * 1024 + j0 + jb);
        *(float4*)&Bs[kb][jb] = b4;
        __syncthreads();

        #pragma unroll
        for (int kk = 0; kk < 8; kk++) {
            float4 a0 = *(float4*)&As[kk][ty * 8];
            float4 a1 = *(float4*)&As[kk][ty * 8 + 4];
            float4 b0 = *(float4*)&Bs[kk][tx * 8];
            float4 b1 = *(float4*)&Bs[kk][tx * 8 + 4];
            float aa[8] = {a0.x, a0.y, a0.z, a0.w, a1.x, a1.y, a1.z, a1.w};
            float bb[8] = {b0.x, b0.y, b0.z, b0.w, b1.x, b1.y, b1.z, b1.w};
            #pragma unroll
            for (int i = 0; i < 8; i++)
                #pragma unroll
                for (int j = 0; j < 8; j++)
                    acc[i][j] = fmaf(aa[i], bb[j], acc[i][j]);
        }
        __syncthreads();
    }

    float4 pb0 = *(const float4*)(pb + j0 + tx * 8);
    float4 pb1 = *(const float4*)(pb + j0 + tx * 8 + 4);
    #pragma unroll
    for (int i = 0; i < 8; i++) {
        float4 o0 = {acc[i][0] + pb0.x, acc[i][1] + pb0.y,
                     acc[i][2] + pb0.z, acc[i][3] + pb0.w};
        float4 o1 = {acc[i][4] + pb1.x, acc[i][5] + pb1.y,
                     acc[i][6] + pb1.z, acc[i][7] + pb1.w};
        float* op = out + (size_t)(row0 + ty * 8 + i) * 1024 + j0 + tx * 8;
        *(float4*)op = o0;
        *(float4*)(op + 4) = o1;
    }
}

// =====================================================================
// launch
// =====================================================================
extern "C" void kernel_launch(void* const* d_in, const int* in_sizes, int n_in,
                              void* d_out, int out_size)
{
    const float* x       = (const float*)d_in[0];
    const float* qkv_w   = (const float*)d_in[1];
    const float* c1      = (const float*)d_in[2];
    const float* c2      = (const float*)d_in[3];
    const float* conv1_w = (const float*)d_in[4];
    const float* gn_g    = (const float*)d_in[5];
    const float* gn_b    = (const float*)d_in[6];
    const float* conv2_w = (const float*)d_in[7];
    const float* conv2_b = (const float*)d_in[8];
    const float* ch_w1   = (const float*)d_in[9];
    const float* ch_b1   = (const float*)d_in[10];
    const float* ch_w2   = (const float*)d_in[11];
    const float* ch_b2   = (const float*)d_in[12];
    const float* proj_w  = (const float*)d_in[13];
    const float* proj_b  = (const float*)d_in[14];
    float* out = (float*)d_out;

    k_mean <<<dim3(16, 8), 1024>>>(x);
    k_gemm1<<<dim3(16, 128), 256>>>(x, qkv_w);
    k_ch   <<<8, 256>>>(ch_w1, ch_b1, ch_w2, ch_b2);
    k_attn <<<64, 256>>>(c1, c2);
    k_ode  <<<8, 256>>>(conv1_w, gn_g, gn_b, conv2_w, conv2_b);
    k_gemm2<<<dim3(8, 128), 256>>>(proj_w, proj_b, out);
}

// round 2
// speedup vs baseline: 2.1109x; 2.1109x over previous
#include <cuda_runtime.h>
#include <math.h>

// Problem constants
#define Bn 8
#define Nn 2048
#define Cn 1024
#define Mrows (Bn*Nn)   // 16384
#define NPART 32        // stats partials: 16 j-tiles x 2 warp-columns

// ---------------- scratch (device globals) ----------------
__device__ float g_v[(size_t)Mrows * Cn];             // 64 MB: v = x @ Wv
__device__ float g_stats[(size_t)NPART * Mrows * 5];  // per-partial row stats
__device__ float g_mpart[16 * Bn * Cn];               // partial column sums of x
__device__ float g_A[Mrows];                          // attn_base / A
__device__ float g_w[Mrows];                          // softmax weights
__device__ float g_chw[Bn * Cn];                      // channel gate

// ---------------- tf32 helpers ----------------
__device__ __forceinline__ unsigned f2tf(float f) {
    unsigned u;
    asm("cvt.rna.tf32.f32 %0, %1;" : "=r"(u) : "f"(f));
    return u;
}
__device__ __forceinline__ void mma8(float* d, const unsigned* a, const unsigned* b) {
    asm volatile(
        "mma.sync.aligned.m16n8k8.row.col.f32.tf32.tf32.f32 "
        "{%0,%1,%2,%3}, {%4,%5,%6,%7}, {%8,%9}, {%0,%1,%2,%3};"
        : "+f"(d[0]), "+f"(d[1]), "+f"(d[2]), "+f"(d[3])
        : "r"(a[0]), "r"(a[1]), "r"(a[2]), "r"(a[3]), "r"(b[0]), "r"(b[1]));
}

// =====================================================================
// GEMM1 (TF32 tensor): qkv = x @ qkv_w
//  block tile: 128(M) x 64(N) x {q,k,v}, BK=32, 256 threads (8 warps 4Mx2N)
//  warp tile 32x32 per matrix -> 2(m16) x 4(n8) mma tiles, fp32 accum
//  epilogue: store v, reduce per-row stats (Sq,Sk,Sqq,Skk,Sqk) per partial
// =====================================================================
#define AS_STRIDE 36
#define BS_STRIDE 72
#define BS_MAT (32 * BS_STRIDE)

__global__ __launch_bounds__(256, 1)
void k_gemm1(const float* __restrict__ x, const float* __restrict__ w)
{
    const int tid = threadIdx.x;
    const int bx = blockIdx.x;          // j tile 0..15 (64 cols)
    const int by = blockIdx.y;          // row tile 0..127
    const int row0 = by * 128;
    const int j0   = bx * 64;
    const int warp = tid >> 5, lane = tid & 31;
    const int wm = warp & 3, wn = warp >> 2;
    const int grp = lane >> 2, qd = lane & 3;

    __shared__ unsigned As[128 * AS_STRIDE];      // 18.4 KB
    __shared__ unsigned Bs[3 * BS_MAT];           // 27.6 KB

    float acc[3][2][4][4];
    #pragma unroll
    for (int t = 0; t < 3; t++)
        #pragma unroll
        for (int mi = 0; mi < 2; mi++)
            #pragma unroll
            for (int ni = 0; ni < 4; ni++)
                #pragma unroll
                for (int j = 0; j < 4; j++) acc[t][mi][ni][j] = 0.f;

    // prefetch registers
    uint4 pa[4];
    uint4 pbf[3][2];

    // per-thread load coords
    const int ar = tid >> 3;                 // A row within tile (uses tid, tid+256..)
    const int ac4 = (tid & 7) * 4;           // A col
    const int bk = tid >> 4;                 // B k row (and +16)
    const int bn4 = (tid & 15) * 4;          // B col

    // ---- load k0 = 0 ----
    {
        const int k0 = 0;
        #pragma unroll
        for (int l = 0; l < 4; l++) {
            int r = ar + l * 32;
            float4 v = *(const float4*)(x + (size_t)(row0 + r) * 1024 + k0 + ac4);
            pa[l] = make_uint4(f2tf(v.x), f2tf(v.y), f2tf(v.z), f2tf(v.w));
        }
        #pragma unroll
        for (int t = 0; t < 3; t++)
            #pragma unroll
            for (int l = 0; l < 2; l++) {
                int k = bk + l * 16;
                float4 v = *(const float4*)(w + (size_t)(k0 + k) * 3072 + t * 1024 + j0 + bn4);
                pbf[t][l] = make_uint4(f2tf(v.x), f2tf(v.y), f2tf(v.z), f2tf(v.w));
            }
    }

    for (int it = 0; it < 32; ++it) {
        // store prefetched tile
        #pragma unroll
        for (int l = 0; l < 4; l++) {
            int r = ar + l * 32;
            *(uint4*)&As[r * AS_STRIDE + ac4] = pa[l];
        }
        #pragma unroll
        for (int t = 0; t < 3; t++)
            #pragma unroll
            for (int l = 0; l < 2; l++) {
                int k = bk + l * 16;
                *(uint4*)&Bs[t * BS_MAT + k * BS_STRIDE + bn4] = pbf[t][l];
            }
        __syncthreads();

        // prefetch next tile (overlaps with mma below)
        if (it < 31) {
            const int k0 = (it + 1) * 32;
            #pragma unroll
            for (int l = 0; l < 4; l++) {
                int r = ar + l * 32;
                float4 v = *(const float4*)(x + (size_t)(row0 + r) * 1024 + k0 + ac4);
                pa[l] = make_uint4(f2tf(v.x), f2tf(v.y), f2tf(v.z), f2tf(v.w));
            }
            #pragma unroll
            for (int t = 0; t < 3; t++)
                #pragma unroll
                for (int l = 0; l < 2; l++) {
                    int k = bk + l * 16;
                    float4 v = *(const float4*)(w + (size_t)(k0 + k) * 3072 + t * 1024 + j0 + bn4);
                    pbf[t][l] = make_uint4(f2tf(v.x), f2tf(v.y), f2tf(v.z), f2tf(v.w));
                }
        }

        // compute 4 k-steps of 8
        #pragma unroll
        for (int kk = 0; kk < 4; kk++) {
            unsigned a[2][4];
            const int c0 = kk * 8 + qd;
            #pragma unroll
            for (int mi = 0; mi < 2; mi++) {
                int base = (wm * 32 + mi * 16 + grp) * AS_STRIDE + c0;
                a[mi][0] = As[base];
                a[mi][1] = As[base + 8 * AS_STRIDE];
                a[mi][2] = As[base + 4];
                a[mi][3] = As[base + 8 * AS_STRIDE + 4];
            }
            #pragma unroll
            for (int t = 0; t < 3; t++) {
                #pragma unroll
                for (int ni = 0; ni < 4; ni++) {
                    unsigned bfr[2];
                    int bidx = t * BS_MAT + (kk * 8 + qd) * BS_STRIDE + wn * 32 + ni * 8 + grp;
                    bfr[0] = Bs[bidx];
                    bfr[1] = Bs[bidx + 4 * BS_STRIDE];
                    mma8(acc[t][0][ni], a[0], bfr);
                    mma8(acc[t][1][ni], a[1], bfr);
                }
            }
        }
        __syncthreads();
    }

    // ---- epilogue: store v (t=2) ----
    #pragma unroll
    for (int mi = 0; mi < 2; mi++) {
        #pragma unroll
        for (int ni = 0; ni < 4; ni++) {
            int rg = row0 + wm * 32 + mi * 16 + grp;
            int cg = j0 + wn * 32 + ni * 8 + qd * 2;
            float2 lo = {acc[2][mi][ni][0], acc[2][mi][ni][1]};
            float2 hi = {acc[2][mi][ni][2], acc[2][mi][ni][3]};
            *(float2*)&g_v[(size_t)rg * 1024 + cg] = lo;
            *(float2*)&g_v[(size_t)(rg + 8) * 1024 + cg] = hi;
        }
    }

    // ---- epilogue: stats (q=t0, k=t1) reduced over quad lanes ----
    const int p = bx * 2 + wn;
    #pragma unroll
    for (int mi = 0; mi < 2; mi++) {
        #pragma unroll
        for (int h = 0; h < 2; h++) {
            float sq = 0.f, sk = 0.f, sqq = 0.f, skk = 0.f, sqk = 0.f;
            #pragma unroll
            for (int ni = 0; ni < 4; ni++) {
                #pragma unroll
                for (int j = 0; j < 2; j++) {
                    float q = acc[0][mi][ni][h * 2 + j];
                    float k = acc[1][mi][ni][h * 2 + j];
                    sq += q; sk += k; sqq += q * q; skk += k * k; sqk += q * k;
                }
            }
            #pragma unroll
            for (int off = 1; off <= 2; off <<= 1) {
                sq  += __shfl_xor_sync(0xffffffffu, sq,  off);
                sk  += __shfl_xor_sync(0xffffffffu, sk,  off);
                sqq += __shfl_xor_sync(0xffffffffu, sqq, off);
                skk += __shfl_xor_sync(0xffffffffu, skk, off);
                sqk += __shfl_xor_sync(0xffffffffu, sqk, off);
            }
            if (qd == 0) {
                int row = row0 + wm * 32 + mi * 16 + grp + h * 8;
                float* d = g_stats + ((size_t)p * Mrows + row) * 5;
                d[0] = sq; d[1] = sk; d[2] = sqq; d[3] = skk; d[4] = sqk;
            }
        }
    }
}

// =====================================================================
// attn_base from stats
// =====================================================================
__global__ void k_attn(const float* __restrict__ c1p, const float* __restrict__ c2p)
{
    int row = blockIdx.x * 256 + threadIdx.x;
    float S0 = 0.f, S1 = 0.f, S2 = 0.f, S3 = 0.f, S4 = 0.f;
    #pragma unroll
    for (int p = 0; p < NPART; p++) {
        const float* d = g_stats + ((size_t)p * Mrows + row) * 5;
        S0 += d[0]; S1 += d[1]; S2 += d[2]; S3 += d[3]; S4 += d[4];
    }
    const float c1 = *c1p, c2 = *c2p;
    const float invC = 1.0f / (float)Cn;
    const float invcm1 = 1.0f / (float)(Cn - 1);
    float muq = S0 * invC, muk = S1 * invC;
    float sqk = (S4 - (float)Cn * muq * muk) * invcm1;
    float sq2 = (S2 - (float)Cn * muq * muq) * invcm1;
    float sk2 = (S3 - (float)Cn * muk * muk) * invcm1;
    float num = (2.f * muq * muk + c1) * (2.f * sqk + c2);
    float den = (muq * muq + muk * muk + c1) * (sq2 + sk2 + c2);
    float r = num / (den + 1e-7f);
    g_A[row] = r * r;
}

// =====================================================================
// column-mean of x over n (16 n-chunk partials)
// =====================================================================
__global__ void k_mean(const float* __restrict__ x)
{
    int p = blockIdx.x, b = blockIdx.y, c = threadIdx.x;
    const float* xp = x + ((size_t)b * Nn + p * 128) * Cn + c;
    float s = 0.f;
    #pragma unroll 4
    for (int n = 0; n < 128; n++) s += xp[(size_t)n * Cn];
    g_mpart[(p * Bn + b) * Cn + c] = s;
}

// =====================================================================
// channel gate
// =====================================================================
__global__ __launch_bounds__(256)
void k_ch(const float* __restrict__ w1, const float* __restrict__ b1,
          const float* __restrict__ w2, const float* __restrict__ b2)
{
    const int b = blockIdx.x, tid = threadIdx.x;
    __shared__ float m[1024];
    __shared__ float h[256];
    for (int c = tid; c < 1024; c += 256) {
        float s = 0.f;
        #pragma unroll
        for (int p = 0; p < 16; p++) s += g_mpart[(p * Bn + b) * Cn + c];
        m[c] = s * (1.0f / (float)Nn);
    }
    __syncthreads();
    {
        float acc = b1[tid];
        #pragma unroll 4
        for (int c = 0; c < 1024; c++) acc = fmaf(m[c], w1[c * 256 + tid], acc);
        h[tid] = fmaxf(acc, 0.f);
    }
    __syncthreads();
    for (int c = tid; c < 1024; c += 256) {
        float a = b2[c];
        #pragma unroll 4
        for (int j = 0; j < 256; j++) a = fmaf(h[j], w2[j * 1024 + c], a);
        g_chw[b * Cn + c] = 1.0f / (1.0f + expf(-a));
    }
}

// =====================================================================
// ODE step + sigmoid + softmax over N
// =====================================================================
__device__ __forceinline__ float blk_sum(float v, float* red, int tid)
{
    red[tid] = v; __syncthreads();
    #pragma unroll
    for (int s = 128; s > 0; s >>= 1) {
        if (tid < s) red[tid] += red[tid + s];
        __syncthreads();
    }
    float r = red[0]; __syncthreads();
    return r;
}
__device__ __forceinline__ float blk_max(float v, float* red, int tid)
{
    red[tid] = v; __syncthreads();
    #pragma unroll
    for (int s = 128; s > 0; s >>= 1) {
        if (tid < s) red[tid] = fmaxf(red[tid], red[tid + s]);
        __syncthreads();
    }
    float r = red[0]; __syncthreads();
    return r;
}

__global__ __launch_bounds__(256)
void k_ode(const float* __restrict__ c1w, const float* __restrict__ gng,
           const float* __restrict__ gnb, const float* __restrict__ c2w,
           const float* __restrict__ c2b)
{
    const int b = blockIdx.x, tid = threadIdx.x;
    __shared__ float A[2048];
    __shared__ float h[4][2048];
    __shared__ float red[256];

    float w1[12], w2[12], gg[4], gb[4];
    #pragma unroll
    for (int t = 0; t < 12; t++) { w1[t] = c1w[t]; w2[t] = c2w[t]; }
    #pragma unroll
    for (int o = 0; o < 4; o++) { gg[o] = gng[o]; gb[o] = gnb[o]; }

    #pragma unroll
    for (int j = 0; j < 8; j++) { int n = tid + j * 256; A[n] = g_A[b * Nn + n]; }
    __syncthreads();

    float s0 = 0.f, ss0 = 0.f, s1 = 0.f, ss1 = 0.f;
    #pragma unroll
    for (int j = 0; j < 8; j++) {
        int n = tid + j * 256;
        float am = (n > 0)    ? A[n - 1] : 0.f;
        float a0 = A[n];
        float ap = (n < 2047) ? A[n + 1] : 0.f;
        #pragma unroll
        for (int o = 0; o < 4; o++) {
            float v = am * w1[o * 3] + a0 * w1[o * 3 + 1] + ap * w1[o * 3 + 2];
            h[o][n] = v;
            if (o < 2) { s0 += v; ss0 += v * v; } else { s1 += v; ss1 += v * v; }
        }
    }
    float S0  = blk_sum(s0,  red, tid);
    float SS0 = blk_sum(ss0, red, tid);
    float S1  = blk_sum(s1,  red, tid);
    float SS1 = blk_sum(ss1, red, tid);
    const float inv = 1.0f / 4096.0f;
    float mu[2] = {S0 * inv, S1 * inv};
    float rs[2] = {rsqrtf(SS0 * inv - mu[0] * mu[0] + 1e-5f),
                   rsqrtf(SS1 * inv - mu[1] * mu[1] + 1e-5f)};

    #pragma unroll
    for (int j = 0; j < 8; j++) {
        int n = tid + j * 256;
        #pragma unroll
        for (int o = 0; o < 4; o++) {
            int g = o >> 1;
            float v = (h[o][n] - mu[g]) * rs[g] * gg[o] + gb[o];
            h[o][n] = v > 0.f ? v : 0.f;
        }
    }
    __syncthreads();

    float fa[8];
    float c2bv = c2b[0];
    float mx = -1e30f;
    #pragma unroll
    for (int j = 0; j < 8; j++) {
        int n = tid + j * 256;
        float y = c2bv;
        #pragma unroll
        for (int o = 0; o < 4; o++) {
            float hm = (n > 0)    ? h[o][n - 1] : 0.f;
            float h0 = h[o][n];
            float hp = (n < 2047) ? h[o][n + 1] : 0.f;
            y += hm * w2[o * 3] + h0 * w2[o * 3 + 1] + hp * w2[o * 3 + 2];
        }
        float An = A[n] + y;
        float f = 1.0f / (1.0f + expf(-An));
        fa[j] = f;
        mx = fmaxf(mx, f);
    }

    float gmax = blk_max(mx, red, tid);
    float se = 0.f;
    #pragma unroll
    for (int j = 0; j < 8; j++) { fa[j] = expf(fa[j] - gmax); se += fa[j]; }
    float tot = blk_sum(se, red, tid);
    float invt = 1.0f / tot;
    #pragma unroll
    for (int j = 0; j < 8; j++) g_w[b * Nn + tid + j * 256] = fa[j] * invt;
}

// =====================================================================
// GEMM2 (TF32 tensor): out = (w * v * ch_w) @ proj_w + proj_b
//  block tile 128x128, BK=32, 256 threads (8 warps 2Mx4N), warp tile 64x32
// =====================================================================
#define BS2_STRIDE 136

__global__ __launch_bounds__(256, 1)
void k_gemm2(const float* __restrict__ pw, const float* __restrict__ pbias,
             float* __restrict__ out)
{
    const int tid = threadIdx.x;
    const int bx = blockIdx.x;          // j tile 0..7
    const int by = blockIdx.y;          // row tile 0..127
    const int row0 = by * 128;
    const int j0   = bx * 128;
    const int b    = row0 >> 11;
    const int warp = tid >> 5, lane = tid & 31;
    const int wm = warp & 1, wn = warp >> 1;
    const int grp = lane >> 2, qd = lane & 3;

    __shared__ unsigned As[128 * AS_STRIDE];     // 18.4 KB
    __shared__ unsigned Bs[32 * BS2_STRIDE];     // 17.4 KB

    float acc[4][4][4];
    #pragma unroll
    for (int mi = 0; mi < 4; mi++)
        #pragma unroll
        for (int ni = 0; ni < 4; ni++)
            #pragma unroll
            for (int j = 0; j < 4; j++) acc[mi][ni][j] = 0.f;

    uint4 pa[4], pbf[4];

    const int ar = tid >> 3;
    const int ac4 = (tid & 7) * 4;
    const int bk = tid >> 5;                 // 0..7 (and +8,+16,+24)
    const int bn4 = (tid & 31) * 4;

    // per-row softmax weight (rows fixed across iters)
    float wr4[4];
    #pragma unroll
    for (int l = 0; l < 4; l++) wr4[l] = g_w[row0 + ar + l * 32];

    // ---- load k0 = 0 ----
    {
        const int k0 = 0;
        #pragma unroll
        for (int l = 0; l < 4; l++) {
            int r = ar + l * 32;
            float4 v = *(const float4*)(g_v + (size_t)(row0 + r) * 1024 + k0 + ac4);
            float4 cw = *(const float4*)(g_chw + b * Cn + k0 + ac4);
            float s = wr4[l];
            pa[l] = make_uint4(f2tf(v.x * s * cw.x), f2tf(v.y * s * cw.y),
                               f2tf(v.z * s * cw.z), f2tf(v.w * s * cw.w));
        }
        #pragma unroll
        for (int l = 0; l < 4; l++) {
            int k = bk + l * 8;
            float4 v = *(const float4*)(pw + (size_t)(k0 + k) * 1024 + j0 + bn4);
            pbf[l] = make_uint4(f2tf(v.x), f2tf(v.y), f2tf(v.z), f2tf(v.w));
        }
    }

    for (int it = 0; it < 32; ++it) {
        #pragma unroll
        for (int l = 0; l < 4; l++) {
            int r = ar + l * 32;
            *(uint4*)&As[r * AS_STRIDE + ac4] = pa[l];
        }
        #pragma unroll
        for (int l = 0; l < 4; l++) {
            int k = bk + l * 8;
            *(uint4*)&Bs[k * BS2_STRIDE + bn4] = pbf[l];
        }
        __syncthreads();

        if (it < 31) {
            const int k0 = (it + 1) * 32;
            #pragma unroll
            for (int l = 0; l < 4; l++) {
                int r = ar + l * 32;
                float4 v = *(const float4*)(g_v + (size_t)(row0 + r) * 1024 + k0 + ac4);
                float4 cw = *(const float4*)(g_chw + b * Cn + k0 + ac4);
                float s = wr4[l];
                pa[l] = make_uint4(f2tf(v.x * s * cw.x), f2tf(v.y * s * cw.y),
                                   f2tf(v.z * s * cw.z), f2tf(v.w * s * cw.w));
            }
            #pragma unroll
            for (int l = 0; l < 4; l++) {
                int k = bk + l * 8;
                float4 v = *(const float4*)(pw + (size_t)(k0 + k) * 1024 + j0 + bn4);
                pbf[l] = make_uint4(f2tf(v.x), f2tf(v.y), f2tf(v.z), f2tf(v.w));
            }
        }

        #pragma unroll
        for (int kk = 0; kk < 4; kk++) {
            unsigned a[4][4];
            const int c0 = kk * 8 + qd;
            #pragma unroll
            for (int mi = 0; mi < 4; mi++) {
                int base = (wm * 64 + mi * 16 + grp) * AS_STRIDE + c0;
                a[mi][0] = As[base];
                a[mi][1] = As[base + 8 * AS_STRIDE];
                a[mi][2] = As[base + 4];
                a[mi][3] = As[base + 8 * AS_STRIDE + 4];
            }
            #pragma unroll
            for (int ni = 0; ni < 4; ni++) {
                unsigned bfr[2];
                int bidx = (kk * 8 + qd) * BS2_STRIDE + wn * 32 + ni * 8 + grp;
                bfr[0] = Bs[bidx];
                bfr[1] = Bs[bidx + 4 * BS2_STRIDE];
                #pragma unroll
                for (int mi = 0; mi < 4; mi++)
                    mma8(acc[mi][ni], a[mi], bfr);
            }
        }
        __syncthreads();
    }

    // epilogue: + bias, store
    #pragma unroll
    for (int mi = 0; mi < 4; mi++) {
        #pragma unroll
        for (int ni = 0; ni < 4; ni++) {
            int rg = row0 + wm * 64 + mi * 16 + grp;
            int cg = j0 + wn * 32 + ni * 8 + qd * 2;
            float2 pb2 = *(const float2*)(pbias + cg);
            float2 lo = {acc[mi][ni][0] + pb2.x, acc[mi][ni][1] + pb2.y};
            float2 hi = {acc[mi][ni][2] + pb2.x, acc[mi][ni][3] + pb2.y};
            *(float2*)&out[(size_t)rg * 1024 + cg] = lo;
            *(float2*)&out[(size_t)(rg + 8) * 1024 + cg] = hi;
        }
    }
}

// =====================================================================
// launch
// =====================================================================
extern "C" void kernel_launch(void* const* d_in, const int* in_sizes, int n_in,
                              void* d_out, int out_size)
{
    const float* x       = (const float*)d_in[0];
    const float* qkv_w   = (const float*)d_in[1];
    const float* c1      = (const float*)d_in[2];
    const float* c2      = (const float*)d_in[3];
    const float* conv1_w = (const float*)d_in[4];
    const float* gn_g    = (const float*)d_in[5];
    const float* gn_b    = (const float*)d_in[6];
    const float* conv2_w = (const float*)d_in[7];
    const float* conv2_b = (const float*)d_in[8];
    const float* ch_w1   = (const float*)d_in[9];
    const float* ch_b1   = (const float*)d_in[10];
    const float* ch_w2   = (const float*)d_in[11];
    const float* ch_b2   = (const float*)d_in[12];
    const float* proj_w  = (const float*)d_in[13];
    const float* proj_b  = (const float*)d_in[14];
    float* out = (float*)d_out;

    k_mean <<<dim3(16, 8), 1024>>>(x);
    k_gemm1<<<dim3(16, 128), 256>>>(x, qkv_w);
    k_ch   <<<8, 256>>>(ch_w1, ch_b1, ch_w2, ch_b2);
    k_attn <<<64, 256>>>(c1, c2);
    k_ode  <<<8, 256>>>(conv1_w, gn_g, gn_b, conv2_w, conv2_b);
    k_gemm2<<<dim3(8, 128), 256>>>(proj_w, proj_b, out);
}

// round 4
// speedup vs baseline: 3.9800x; 1.8854x over previous
#include <cuda_runtime.h>
#include <cuda_fp16.h>
#include <math.h>
#include <stdint.h>

// Problem constants
#define Bn 8
#define Nn 2048
#define Cn 1024
#define Mrows (Bn*Nn)   // 16384
#define NPART 32        // stats partials: 16 j-tiles x 2 warp-columns

// ---------------- scratch (device globals) ----------------
__device__ __half g_xh[(size_t)Mrows * Cn];            // 32 MB: fp16(x)
__device__ __half g_wth[(size_t)3072 * 1024];          // 6 MB: fp16(qkv_w^T) [j][k]
__device__ __half g_pw2h[(size_t)Bn * 1024 * 1024];    // 16 MB: fp16(chw[b][k]*proj_w[k][j]) [b][j][k]
__device__ __half g_vh[(size_t)Mrows * Cn];            // 32 MB: fp16(v)
__device__ float g_stats[(size_t)NPART * Mrows * 5];
__device__ float g_mpart[16 * Bn * Cn];
__device__ float g_A[Mrows];
__device__ float g_w[Mrows];
__device__ float g_chw[Bn * Cn];

// ---------------- helpers ----------------
__device__ __forceinline__ uint32_t smem_u32(const void* p) {
    uint32_t a;
    asm("{ .reg .u64 t; cvta.to.shared.u64 t, %1; cvt.u32.u64 %0, t; }" : "=r"(a) : "l"(p));
    return a;
}
__device__ __forceinline__ void cp16(uint32_t dst, const void* src) {
    asm volatile("cp.async.cg.shared.global [%0], [%1], 16;" :: "r"(dst), "l"(src));
}
__device__ __forceinline__ void cp_commit() { asm volatile("cp.async.commit_group;" ::: "memory"); }
template<int N> __device__ __forceinline__ void cp_wait() {
    asm volatile("cp.async.wait_group %0;" :: "n"(N) : "memory");
}
__device__ __forceinline__ void ldsm4(uint32_t* r, uint32_t a) {
    asm volatile("ldmatrix.sync.aligned.m8n8.x4.shared.b16 {%0,%1,%2,%3}, [%4];"
                 : "=r"(r[0]), "=r"(r[1]), "=r"(r[2]), "=r"(r[3]) : "r"(a));
}
__device__ __forceinline__ void mma16(float* d, const uint32_t* a, const uint32_t* b) {
    asm volatile(
        "mma.sync.aligned.m16n8k16.row.col.f32.f16.f16.f32 "
        "{%0,%1,%2,%3}, {%4,%5,%6,%7}, {%8,%9}, {%0,%1,%2,%3};"
        : "+f"(d[0]), "+f"(d[1]), "+f"(d[2]), "+f"(d[3])
        : "r"(a[0]), "r"(a[1]), "r"(a[2]), "r"(a[3]), "r"(b[0]), "r"(b[1]));
}

// =====================================================================
// prep kernels (fp32 -> fp16 operand staging)
// =====================================================================
__global__ void k_prep_x(const float* __restrict__ x) {
    size_t i = ((size_t)blockIdx.x * 256 + threadIdx.x) * 8;
    float4 v0 = *(const float4*)(x + i);
    float4 v1 = *(const float4*)(x + i + 4);
    union { __half2 h[4]; uint4 u; } c;
    c.h[0] = __floats2half2_rn(v0.x, v0.y);
    c.h[1] = __floats2half2_rn(v0.z, v0.w);
    c.h[2] = __floats2half2_rn(v1.x, v1.y);
    c.h[3] = __floats2half2_rn(v1.z, v1.w);
    *(uint4*)(g_xh + i) = c.u;
}
__global__ void k_prep_w(const float* __restrict__ w) {   // [1024][3072] -> g_wth[3072][1024]
    __shared__ float t[32][33];
    int j0 = blockIdx.x * 32, k0 = blockIdx.y * 32;
    int tx = threadIdx.x, ty = threadIdx.y;
    #pragma unroll
    for (int l = 0; l < 4; l++)
        t[ty + l * 8][tx] = w[(size_t)(k0 + ty + l * 8) * 3072 + j0 + tx];
    __syncthreads();
    #pragma unroll
    for (int l = 0; l < 4; l++)
        g_wth[(size_t)(j0 + ty + l * 8) * 1024 + k0 + tx] = __float2half_rn(t[tx][ty + l * 8]);
}
__global__ void k_prep_pw(const float* __restrict__ pw) { // [1024][1024] -> g_pw2h[b][j][k]
    __shared__ float t[32][33];
    int j0 = blockIdx.x * 32, k0 = blockIdx.y * 32, b = blockIdx.z;
    int tx = threadIdx.x, ty = threadIdx.y;
    #pragma unroll
    for (int l = 0; l < 4; l++)
        t[ty + l * 8][tx] = pw[(size_t)(k0 + ty + l * 8) * 1024 + j0 + tx];
    __syncthreads();
    float cw = g_chw[b * Cn + k0 + tx];
    #pragma unroll
    for (int l = 0; l < 4; l++)
        g_pw2h[((size_t)b * 1024 + j0 + ty + l * 8) * 1024 + k0 + tx] =
            __float2half_rn(t[tx][ty + l * 8] * cw);
}

// =====================================================================
// GEMM1 (fp16 mma.sync): qkv = x @ qkv_w
//  block 128m x 64n x {q,k,v}, k-chunk 32, 3-stage cp.async ring
//  8 warps (4m x 2n), warp tile 32m x 32n x 3 mats, ldmatrix.x4 fragments
//  epilogue: store v fp16, per-row stats for q,k
// =====================================================================
#define G1_A 10240              // 128 rows * 80B
#define G1_B 5120               // 64 rows * 80B (per matrix)
#define G1_STAGE (G1_A + 3*G1_B)   // 25600
#define G1_NS 3

__device__ __forceinline__ void g1_fill(uint32_t sbase, int k0, int row0, int j0, int tid)
{
    #pragma unroll
    for (int i = 0; i < 2; i++) {
        int e = tid + i * 256;               // 0..511
        int r = e >> 2, c = e & 3;
        cp16(sbase + r * 80 + c * 16, g_xh + (size_t)(row0 + r) * 1024 + k0 + c * 8);
    }
    #pragma unroll
    for (int i = 0; i < 3; i++) {
        int e = tid + i * 256;               // 0..767
        int t = e >> 8, rr = (e >> 2) & 63, c = e & 3;
        cp16(sbase + G1_A + t * G1_B + rr * 80 + c * 16,
             g_wth + (size_t)(t * 1024 + j0 + rr) * 1024 + k0 + c * 8);
    }
    cp_commit();
}

__global__ __launch_bounds__(256, 1)
void k_gemm1()
{
    extern __shared__ __align__(128) char smem[];
    const uint32_t sb = smem_u32(smem);
    const int tid = threadIdx.x;
    const int wid = tid >> 5, lane = tid & 31;
    const int wm = wid & 3, wn = wid >> 2;
    const int grp = lane >> 2, qd = lane & 3;
    const int lr = lane & 15, lc = lane >> 4;
    const int j0 = blockIdx.x * 64;
    const int row0 = blockIdx.y * 128;

    float acc[3][2][4][4];
    #pragma unroll
    for (int t = 0; t < 3; t++)
        #pragma unroll
        for (int mi = 0; mi < 2; mi++)
            #pragma unroll
            for (int ni = 0; ni < 4; ni++)
                #pragma unroll
                for (int j = 0; j < 4; j++) acc[t][mi][ni][j] = 0.f;

    g1_fill(sb + 0 * G1_STAGE, 0,  row0, j0, tid);
    g1_fill(sb + 1 * G1_STAGE, 32, row0, j0, tid);

    for (int it = 0; it < 32; ++it) {
        cp_wait<G1_NS - 2>();
        __syncthreads();
        int fc = it + G1_NS - 1;
        if (fc < 32) g1_fill(sb + (fc % G1_NS) * G1_STAGE, fc * 32, row0, j0, tid);
        else cp_commit();   // keep per-thread group count invariant

        const uint32_t Ab = sb + (it % G1_NS) * G1_STAGE;
        const uint32_t Bb = Ab + G1_A;
        #pragma unroll
        for (int kk = 0; kk < 2; kk++) {
            uint32_t a[2][4];
            #pragma unroll
            for (int mi = 0; mi < 2; mi++)
                ldsm4(a[mi], Ab + (uint32_t)((wm * 32 + mi * 16 + lr) * 80 + (kk * 2 + lc) * 16));
            #pragma unroll
            for (int t = 0; t < 3; t++) {
                #pragma unroll
                for (int hh = 0; hh < 2; hh++) {
                    uint32_t bb[4];
                    ldsm4(bb, Bb + (uint32_t)(t * G1_B + (wn * 32 + hh * 16 + lr) * 80 + (kk * 2 + lc) * 16));
                    uint32_t b0[2] = {bb[0], bb[2]};
                    uint32_t b1[2] = {bb[1], bb[3]};
                    #pragma unroll
                    for (int mi = 0; mi < 2; mi++) {
                        mma16(acc[t][mi][hh * 2],     a[mi], b0);
                        mma16(acc[t][mi][hh * 2 + 1], a[mi], b1);
                    }
                }
            }
        }
    }

    // ---- epilogue: v (mat 2) -> fp16 ----
    #pragma unroll
    for (int mi = 0; mi < 2; mi++) {
        #pragma unroll
        for (int ni = 0; ni < 4; ni++) {
            int rg = row0 + wm * 32 + mi * 16 + grp;
            int cg = j0 + wn * 32 + ni * 8 + qd * 2;
            *(__half2*)&g_vh[(size_t)rg * 1024 + cg] =
                __floats2half2_rn(acc[2][mi][ni][0], acc[2][mi][ni][1]);
            *(__half2*)&g_vh[(size_t)(rg + 8) * 1024 + cg] =
                __floats2half2_rn(acc[2][mi][ni][2], acc[2][mi][ni][3]);
        }
    }

    // ---- epilogue: stats for q (mat 0), k (mat 1); reduce over quad lanes ----
    const int p = blockIdx.x * 2 + wn;
    #pragma unroll
    for (int mi = 0; mi < 2; mi++) {
        #pragma unroll
        for (int h = 0; h < 2; h++) {
            float sq = 0.f, sk = 0.f, sqq = 0.f, skk = 0.f, sqk = 0.f;
            #pragma unroll
            for (int ni = 0; ni < 4; ni++) {
                #pragma unroll
                for (int j = 0; j < 2; j++) {
                    float q = acc[0][mi][ni][h * 2 + j];
                    float k = acc[1][mi][ni][h * 2 + j];
                    sq += q; sk += k; sqq += q * q; skk += k * k; sqk += q * k;
                }
            }
            #pragma unroll
            for (int off = 1; off <= 2; off <<= 1) {
                sq  += __shfl_xor_sync(0xffffffffu, sq,  off);
                sk  += __shfl_xor_sync(0xffffffffu, sk,  off);
                sqq += __shfl_xor_sync(0xffffffffu, sqq, off);
                skk += __shfl_xor_sync(0xffffffffu, skk, off);
                sqk += __shfl_xor_sync(0xffffffffu, sqk, off);
            }
            if (qd == 0) {
                int row = row0 + wm * 32 + mi * 16 + grp + h * 8;
                float* d = g_stats + ((size_t)p * Mrows + row) * 5;
                d[0] = sq; d[1] = sk; d[2] = sqq; d[3] = skk; d[4] = sqk;
            }
        }
    }
}

// =====================================================================
// GEMM2 (fp16 mma.sync): out = diag(w_softmax) * (v @ pw2[b]) + bias
//  block 128m x 128n, k-chunk 32, 3 stages, 8 warps (2m x 4n), warp 64m x 32n
// =====================================================================
#define G2_A 10240
#define G2_B 10240
#define G2_STAGE (G2_A + G2_B)     // 20480
#define G2_NS 3

__device__ __forceinline__ void g2_fill(uint32_t sbase, int k0, int row0, int j0, int b, int tid)
{
    #pragma unroll
    for (int i = 0; i < 2; i++) {
        int e = tid + i * 256;
        int r = e >> 2, c = e & 3;
        cp16(sbase + r * 80 + c * 16, g_vh + (size_t)(row0 + r) * 1024 + k0 + c * 8);
    }
    #pragma unroll
    for (int i = 0; i < 2; i++) {
        int e = tid + i * 256;
        int rr = e >> 2, c = e & 3;
        cp16(sbase + G2_A + rr * 80 + c * 16,
             g_pw2h + ((size_t)b * 1024 + j0 + rr) * 1024 + k0 + c * 8);
    }
    cp_commit();
}

__global__ __launch_bounds__(256, 1)
void k_gemm2(const float* __restrict__ pbias, float* __restrict__ out)
{
    extern __shared__ __align__(128) char smem[];
    const uint32_t sb = smem_u32(smem);
    const int tid = threadIdx.x;
    const int wid = tid >> 5, lane = tid & 31;
    const int wm = wid & 1, wn = wid >> 1;
    const int grp = lane >> 2, qd = lane & 3;
    const int lr = lane & 15, lc = lane >> 4;
    const int j0 = blockIdx.x * 128;
    const int row0 = blockIdx.y * 128;
    const int b = row0 >> 11;

    float acc[4][4][4];
    #pragma unroll
    for (int mi = 0; mi < 4; mi++)
        #pragma unroll
        for (int ni = 0; ni < 4; ni++)
            #pragma unroll
            for (int j = 0; j < 4; j++) acc[mi][ni][j] = 0.f;

    g2_fill(sb + 0 * G2_STAGE, 0,  row0, j0, b, tid);
    g2_fill(sb + 1 * G2_STAGE, 32, row0, j0, b, tid);

    for (int it = 0; it < 32; ++it) {
        cp_wait<G2_NS - 2>();
        __syncthreads();
        int fc = it + G2_NS - 1;
        if (fc < 32) g2_fill(sb + (fc % G2_NS) * G2_STAGE, fc * 32, row0, j0, b, tid);
        else cp_commit();

        const uint32_t Ab = sb + (it % G2_NS) * G2_STAGE;
        const uint32_t Bb = Ab + G2_A;
        #pragma unroll
        for (int kk = 0; kk < 2; kk++) {
            uint32_t a[4][4];
            #pragma unroll
            for (int mi = 0; mi < 4; mi++)
                ldsm4(a[mi], Ab + (uint32_t)((wm * 64 + mi * 16 + lr) * 80 + (kk * 2 + lc) * 16));
            #pragma unroll
            for (int hh = 0; hh < 2; hh++) {
                uint32_t bb[4];
                ldsm4(bb, Bb + (uint32_t)((wn * 32 + hh * 16 + lr) * 80 + (kk * 2 + lc) * 16));
                uint32_t b0[2] = {bb[0], bb[2]};
                uint32_t b1[2] = {bb[1], bb[3]};
                #pragma unroll
                for (int mi = 0; mi < 4; mi++) {
                    mma16(acc[mi][hh * 2],     a[mi], b0);
                    mma16(acc[mi][hh * 2 + 1], a[mi], b1);
                }
            }
        }
    }

    // epilogue: scale by per-row softmax weight, add bias, store fp32
    #pragma unroll
    for (int mi = 0; mi < 4; mi++) {
        int rgl = row0 + wm * 64 + mi * 16 + grp;
        float wrl = g_w[rgl];
        float wrh = g_w[rgl + 8];
        #pragma unroll
        for (int ni = 0; ni < 4; ni++) {
            int cg = j0 + wn * 32 + ni * 8 + qd * 2;
            float2 pb2 = *(const float2*)(pbias + cg);
            float2 lo = {acc[mi][ni][0] * wrl + pb2.x, acc[mi][ni][1] * wrl + pb2.y};
            float2 hi = {acc[mi][ni][2] * wrh + pb2.x, acc[mi][ni][3] * wrh + pb2.y};
            *(float2*)&out[(size_t)rgl * 1024 + cg] = lo;
            *(float2*)&out[(size_t)(rgl + 8) * 1024 + cg] = hi;
        }
    }
}

// =====================================================================
// attn_base from stats
// =====================================================================
__global__ void k_attn(const float* __restrict__ c1p, const float* __restrict__ c2p)
{
    int row = blockIdx.x * 256 + threadIdx.x;
    float S0 = 0.f, S1 = 0.f, S2 = 0.f, S3 = 0.f, S4 = 0.f;
    #pragma unroll
    for (int p = 0; p < NPART; p++) {
        const float* d = g_stats + ((size_t)p * Mrows + row) * 5;
        S0 += d[0]; S1 += d[1]; S2 += d[2]; S3 += d[3]; S4 += d[4];
    }
    const float c1 = *c1p, c2 = *c2p;
    const float invC = 1.0f / (float)Cn;
    const float invcm1 = 1.0f / (float)(Cn - 1);
    float muq = S0 * invC, muk = S1 * invC;
    float sqk = (S4 - (float)Cn * muq * muk) * invcm1;
    float sq2 = (S2 - (float)Cn * muq * muq) * invcm1;
    float sk2 = (S3 - (float)Cn * muk * muk) * invcm1;
    float num = (2.f * muq * muk + c1) * (2.f * sqk + c2);
    float den = (muq * muq + muk * muk + c1) * (sq2 + sk2 + c2);
    float r = num / (den + 1e-7f);
    g_A[row] = r * r;
}

// =====================================================================
// column-mean of x over n
// =====================================================================
__global__ void k_mean(const float* __restrict__ x)
{
    int p = blockIdx.x, b = blockIdx.y, c = threadIdx.x;
    const float* xp = x + ((size_t)b * Nn + p * 128) * Cn + c;
    float s = 0.f;
    #pragma unroll 4
    for (int n = 0; n < 128; n++) s += xp[(size_t)n * Cn];
    g_mpart[(p * Bn + b) * Cn + c] = s;
}

// =====================================================================
// channel gate
// =====================================================================
__global__ __launch_bounds__(256)
void k_ch(const float* __restrict__ w1, const float* __restrict__ b1,
          const float* __restrict__ w2, const float* __restrict__ b2)
{
    const int b = blockIdx.x, tid = threadIdx.x;
    __shared__ float m[1024];
    __shared__ float h[256];
    for (int c = tid; c < 1024; c += 256) {
        float s = 0.f;
        #pragma unroll
        for (int p = 0; p < 16; p++) s += g_mpart[(p * Bn + b) * Cn + c];
        m[c] = s * (1.0f / (float)Nn);
    }
    __syncthreads();
    {
        float acc = b1[tid];
        #pragma unroll 4
        for (int c = 0; c < 1024; c++) acc = fmaf(m[c], w1[c * 256 + tid], acc);
        h[tid] = fmaxf(acc, 0.f);
    }
    __syncthreads();
    for (int c = tid; c < 1024; c += 256) {
        float a = b2[c];
        #pragma unroll 4
        for (int j = 0; j < 256; j++) a = fmaf(h[j], w2[j * 1024 + c], a);
        g_chw[b * Cn + c] = 1.0f / (1.0f + expf(-a));
    }
}

// =====================================================================
// ODE step + sigmoid + softmax over N
// =====================================================================
__device__ __forceinline__ float blk_sum(float v, float* red, int tid)
{
    red[tid] = v; __syncthreads();
    #pragma unroll
    for (int s = 128; s > 0; s >>= 1) {
        if (tid < s) red[tid] += red[tid + s];
        __syncthreads();
    }
    float r = red[0]; __syncthreads();
    return r;
}
__device__ __forceinline__ float blk_max(float v, float* red, int tid)
{
    red[tid] = v; __syncthreads();
    #pragma unroll
    for (int s = 128; s > 0; s >>= 1) {
        if (tid < s) red[tid] = fmaxf(red[tid], red[tid + s]);
        __syncthreads();
    }
    float r = red[0]; __syncthreads();
    return r;
}

__global__ __launch_bounds__(256)
void k_ode(const float* __restrict__ c1w, const float* __restrict__ gng,
           const float* __restrict__ gnb, const float* __restrict__ c2w,
           const float* __restrict__ c2b)
{
    const int b = blockIdx.x, tid = threadIdx.x;
    __shared__ float A[2048];
    __shared__ float h[4][2048];
    __shared__ float red[256];

    float w1[12], w2[12], gg[4], gb[4];
    #pragma unroll
    for (int t = 0; t < 12; t++) { w1[t] = c1w[t]; w2[t] = c2w[t]; }
    #pragma unroll
    for (int o = 0; o < 4; o++) { gg[o] = gng[o]; gb[o] = gnb[o]; }

    #pragma unroll
    for (int j = 0; j < 8; j++) { int n = tid + j * 256; A[n] = g_A[b * Nn + n]; }
    __syncthreads();

    float s0 = 0.f, ss0 = 0.f, s1 = 0.f, ss1 = 0.f;
    #pragma unroll
    for (int j = 0; j < 8; j++) {
        int n = tid + j * 256;
        float am = (n > 0)    ? A[n - 1] : 0.f;
        float a0 = A[n];
        float ap = (n < 2047) ? A[n + 1] : 0.f;
        #pragma unroll
        for (int o = 0; o < 4; o++) {
            float v = am * w1[o * 3] + a0 * w1[o * 3 + 1] + ap * w1[o * 3 + 2];
            h[o][n] = v;
            if (o < 2) { s0 += v; ss0 += v * v; } else { s1 += v; ss1 += v * v; }
        }
    }
    float S0  = blk_sum(s0,  red, tid);
    float SS0 = blk_sum(ss0, red, tid);
    float S1  = blk_sum(s1,  red, tid);
    float SS1 = blk_sum(ss1, red, tid);
    const float inv = 1.0f / 4096.0f;
    float mu[2] = {S0 * inv, S1 * inv};
    float rs[2] = {rsqrtf(SS0 * inv - mu[0] * mu[0] + 1e-5f),
                   rsqrtf(SS1 * inv - mu[1] * mu[1] + 1e-5f)};

    #pragma unroll
    for (int j = 0; j < 8; j++) {
        int n = tid + j * 256;
        #pragma unroll
        for (int o = 0; o < 4; o++) {
            int g = o >> 1;
            float v = (h[o][n] - mu[g]) * rs[g] * gg[o] + gb[o];
            h[o][n] = v > 0.f ? v : 0.f;
        }
    }
    __syncthreads();

    float fa[8];
    float c2bv = c2b[0];
    float mx = -1e30f;
    #pragma unroll
    for (int j = 0; j < 8; j++) {
        int n = tid + j * 256;
        float y = c2bv;
        #pragma unroll
        for (int o = 0; o < 4; o++) {
            float hm = (n > 0)    ? h[o][n - 1] : 0.f;
            float h0 = h[o][n];
            float hp = (n < 2047) ? h[o][n + 1] : 0.f;
            y += hm * w2[o * 3] + h0 * w2[o * 3 + 1] + hp * w2[o * 3 + 2];
        }
        float An = A[n] + y;
        float f = 1.0f / (1.0f + expf(-An));
        fa[j] = f;
        mx = fmaxf(mx, f);
    }

    float gmax = blk_max(mx, red, tid);
    float se = 0.f;
    #pragma unroll
    for (int j = 0; j < 8; j++) { fa[j] = expf(fa[j] - gmax); se += fa[j]; }
    float tot = blk_sum(se, red, tid);
    float invt = 1.0f / tot;
    #pragma unroll
    for (int j = 0; j < 8; j++) g_w[b * Nn + tid + j * 256] = fa[j] * invt;
}

// =====================================================================
// launch
// =====================================================================
extern "C" void kernel_launch(void* const* d_in, const int* in_sizes, int n_in,
                              void* d_out, int out_size)
{
    const float* x       = (const float*)d_in[0];
    const float* qkv_w   = (const float*)d_in[1];
    const float* c1      = (const float*)d_in[2];
    const float* c2      = (const float*)d_in[3];
    const float* conv1_w = (const float*)d_in[4];
    const float* gn_g    = (const float*)d_in[5];
    const float* gn_b    = (const float*)d_in[6];
    const float* conv2_w = (const float*)d_in[7];
    const float* conv2_b = (const float*)d_in[8];
    const float* ch_w1   = (const float*)d_in[9];
    const float* ch_b1   = (const float*)d_in[10];
    const float* ch_w2   = (const float*)d_in[11];
    const float* ch_b2   = (const float*)d_in[12];
    const float* proj_w  = (const float*)d_in[13];
    const float* proj_b  = (const float*)d_in[14];
    float* out = (float*)d_out;

    cudaFuncSetAttribute(k_gemm1, cudaFuncAttributeMaxDynamicSharedMemorySize, G1_NS * G1_STAGE);
    cudaFuncSetAttribute(k_gemm2, cudaFuncAttributeMaxDynamicSharedMemorySize, G2_NS * G2_STAGE);

    k_prep_x <<<8192, 256>>>(x);
    k_prep_w <<<dim3(96, 32), dim3(32, 8)>>>(qkv_w);
    k_mean   <<<dim3(16, 8), 1024>>>(x);
    k_gemm1  <<<dim3(16, 128), 256, G1_NS * G1_STAGE>>>();
    k_ch     <<<8, 256>>>(ch_w1, ch_b1, ch_w2, ch_b2);
    k_prep_pw<<<dim3(32, 32, 8), dim3(32, 8)>>>(proj_w);
    k_attn   <<<64, 256>>>(c1, c2);
    k_ode    <<<8, 256>>>(conv1_w, gn_g, gn_b, conv2_w, conv2_b);
    k_gemm2  <<<dim3(8, 128), 256, G2_NS * G2_STAGE>>>(proj_b, out);
}